// round 14
// baseline (speedup 1.0000x reference)
#include <cuda_runtime.h>
#include <cuda_fp16.h>
#include <cstdint>

// Problem constants
#define B_NODES 100000
#define U_NODES 50000
#define NTOT    150000
#define F_DIM   512
#define D_DIM   128
#define K_NEIGH 10
#define KOUT    1152

#define SMEM_SWIZZLE_128B(byte_offset) ((byte_offset) ^ (((byte_offset) >> 3) & 0x70))

// ---------------------------------------------------------------------------
// Warp-level tensor-core primitives
// ---------------------------------------------------------------------------
__device__ __forceinline__ uint32_t smem_u32(const void* p) {
    uint32_t a;
    asm("{ .reg .u64 t; cvta.to.shared.u64 t, %1; cvt.u32.u64 %0, t; }" : "=r"(a) : "l"(p));
    return a;
}

__device__ __forceinline__ void ldm_x4(uint32_t* r, uint32_t addr) {
    asm volatile("ldmatrix.sync.aligned.m8n8.x4.shared.b16 {%0,%1,%2,%3}, [%4];"
        : "=r"(r[0]), "=r"(r[1]), "=r"(r[2]), "=r"(r[3]) : "r"(addr));
}

__device__ __forceinline__ void mma_f16(float* c, const uint32_t* a,
                                        uint32_t b0, uint32_t b1) {
    asm volatile("mma.sync.aligned.m16n8k16.row.col.f32.f16.f16.f32 "
        "{%0,%1,%2,%3}, {%4,%5,%6,%7}, {%8,%9}, {%0,%1,%2,%3};"
        : "+f"(c[0]), "+f"(c[1]), "+f"(c[2]), "+f"(c[3])
        : "r"(a[0]), "r"(a[1]), "r"(a[2]), "r"(a[3]), "r"(b0), "r"(b1));
}

__device__ __forceinline__ uint32_t pack_h2(float x, float y) {
    __half2 h = __float22half2_rn(make_float2(x, y));
    return *reinterpret_cast<uint32_t*>(&h);
}

__device__ __forceinline__ void cp_async16(uint32_t dst, const void* src) {
    asm volatile("cp.async.cg.shared.global [%0], [%1], 16;" :: "r"(dst), "l"(src) : "memory");
}
#define CP_ASYNC_COMMIT() asm volatile("cp.async.commit_group;" ::: "memory")
#define CP_ASYNC_WAIT0()  asm volatile("cp.async.wait_group 0;" ::: "memory")

#define STS128(a0, a1, a2, a3, addr) \
    asm volatile("st.shared.v4.b32 [%0], {%1, %2, %3, %4};" \
        :: "r"(addr), "r"(a0), "r"(a1), "r"(a2), "r"(a3) : "memory")
#define STS32(addr, v) \
    asm volatile("st.shared.b32 [%0], %1;" :: "r"(addr), "r"(v) : "memory")

// ---------------------------------------------------------------------------
// Device-global scratch (device-code references only)
// ---------------------------------------------------------------------------
__device__ float g_s[NTOT];
// fp16 h for NEIGHBOR rows only, [U][128]
__device__ __align__(16) __half g_h16[(size_t)U_NODES * D_DIM];
// fp16 partial = fb @ Wd[0:512]  [B][128]
__device__ __align__(16) __half g_partial16[(size_t)B_NODES * D_DIM];
// fp16 transposed weights: [N=128][K]
__device__ __align__(16) __half g_W16_1[(size_t)D_DIM * F_DIM];
__device__ __align__(16) __half g_W16_2[(size_t)D_DIM * KOUT];

// ---------------------------------------------------------------------------
// Weight transpose + fp16 rounding: src [K][128] fp32 -> dstT [128][K] fp16
// ---------------------------------------------------------------------------
template <int WHICH>
__global__ void convertW_kernel(const float* __restrict__ src)
{
    constexpr int K = (WHICH == 1) ? F_DIM : KOUT;
    __half* dstT = (WHICH == 1) ? g_W16_1 : g_W16_2;

    int idx = blockIdx.x * blockDim.x + threadIdx.x;
    if (idx >= K * D_DIM) return;
    int k = idx >> 7, n = idx & 127;
    dstT[(size_t)n * K + k] = __float2half_rn(src[idx]);
}

// ---------------------------------------------------------------------------
// FB pass: N=256 concat GEMM [W | Wd[0:512]], K=512. 128x256 CTA tile, BK=64,
// 512 threads (16 warps, 4Mx4N), 2-stage, 96KB smem, 1 CTA/SM.
// Epilogue: cols [0,128) -> s; cols [128,256) -> fp16 partial.  (round-13)
// ---------------------------------------------------------------------------
__global__ void __launch_bounds__(512, 1)
fb_kernel(const float* __restrict__ fb, const float* __restrict__ avec)
{
    constexpr int NCHUNK = F_DIM / 64;

    extern __shared__ char dsm[];
    const uint32_t ab = (smem_u32(dsm) + 1023u) & ~1023u;

    const int tid = threadIdx.x;
    const int lane = tid & 31;
    const int wid = tid >> 5;
    const int wm = wid & 3;
    const int wn = wid >> 2;
    const int rowBase = blockIdx.x * 128;

    float acc[2][8][4];
    #pragma unroll
    for (int i = 0; i < 2; ++i)
        #pragma unroll
        for (int j = 0; j < 8; ++j)
            #pragma unroll
            for (int q = 0; q < 4; ++q) acc[i][j][q] = 0.f;

    const int lr = lane & 7;
    const int lg = lane >> 3;

    float4 sa0[2], sa1[2];

    auto stA = [&](int s) { return ab + (uint32_t)s * 49152u; };
    auto stB = [&](int s) { return ab + (uint32_t)s * 49152u + 16384u; };

    auto issueLoads = [&](int c, int s) {
        const int k0c = c * 64;
        #pragma unroll
        for (int i = 0; i < 2; ++i) {
            int idx = tid + i * 512;
            int row = idx >> 3, seg = idx & 7;
            int grow = rowBase + row;
            sa0[i] = make_float4(0.f, 0.f, 0.f, 0.f);
            sa1[i] = sa0[i];
            if (grow < B_NODES) {
                const float* src = fb + (size_t)grow * F_DIM + k0c + seg * 8;
                sa0[i] = *(const float4*)(src);
                sa1[i] = *(const float4*)(src + 4);
            }
        }
        #pragma unroll
        for (int i = 0; i < 4; ++i) {
            int idx = tid + i * 512;
            int row = idx >> 3, seg = idx & 7;
            uint32_t off = SMEM_SWIZZLE_128B((uint32_t)(row * 128 + seg * 16));
            const __half* src = (row < 128)
                ? g_W16_1 + (size_t)row * F_DIM + k0c + seg * 8
                : g_W16_2 + (size_t)(row - 128) * KOUT + k0c + seg * 8;
            cp_async16(stB(s) + off, src);
        }
        CP_ASYNC_COMMIT();
    };

    auto commitLoads = [&](int s) {
        #pragma unroll
        for (int i = 0; i < 2; ++i) {
            int idx = tid + i * 512;
            int row = idx >> 3, seg = idx & 7;
            uint32_t w0 = pack_h2(sa0[i].x, sa0[i].y);
            uint32_t w1 = pack_h2(sa0[i].z, sa0[i].w);
            uint32_t w2 = pack_h2(sa1[i].x, sa1[i].y);
            uint32_t w3 = pack_h2(sa1[i].z, sa1[i].w);
            uint32_t off = SMEM_SWIZZLE_128B((uint32_t)(row * 128 + seg * 16));
            STS128(w0, w1, w2, w3, stA(s) + off);
        }
        CP_ASYNC_WAIT0();
    };

    auto computeChunk = [&](int s) {
        #pragma unroll
        for (int t = 0; t < 4; ++t) {
            uint32_t af[2][4];
            #pragma unroll
            for (int i = 0; i < 2; ++i) {
                int row = wm * 32 + i * 16 + lr + (lg & 1) * 8;
                int kb = t * 32 + (lg >> 1) * 16;
                ldm_x4(af[i], stA(s) + SMEM_SWIZZLE_128B((uint32_t)(row * 128 + kb)));
            }
            uint32_t bfr[4][4];
            #pragma unroll
            for (int j = 0; j < 4; ++j) {
                int row = wn * 64 + j * 16 + lr + (lg >> 1) * 8;
                int kb = t * 32 + (lg & 1) * 16;
                ldm_x4(bfr[j], stB(s) + SMEM_SWIZZLE_128B((uint32_t)(row * 128 + kb)));
            }
            #pragma unroll
            for (int i = 0; i < 2; ++i)
                #pragma unroll
                for (int j = 0; j < 4; ++j) {
                    mma_f16(acc[i][2 * j],     af[i], bfr[j][0], bfr[j][1]);
                    mma_f16(acc[i][2 * j + 1], af[i], bfr[j][2], bfr[j][3]);
                }
        }
    };

    issueLoads(0, 0);
    commitLoads(0);
    __syncthreads();

    for (int c = 0; c < NCHUNK; ++c) {
        const int cur = c & 1, nxt = (c + 1) & 1;
        if (c + 1 < NCHUNK) issueLoads(c + 1, nxt);
        computeChunk(cur);
        if (c + 1 < NCHUNK) commitLoads(nxt);
        __syncthreads();
    }

    const int qm = lane >> 2;
    const int qn = (lane & 3) * 2;

    float* s_sm = (float*)dsm;
    if (tid < 128) s_sm[tid] = 0.f;
    __syncthreads();

    if (wn < 2) {
        #pragma unroll
        for (int i = 0; i < 2; ++i) {
            int m0 = wm * 32 + i * 16;
            float s0 = 0.f, s1 = 0.f;
            #pragma unroll
            for (int j = 0; j < 8; ++j) {
                int n = wn * 64 + j * 8 + qn;
                s0 += acc[i][j][0] * avec[n] + acc[i][j][1] * avec[n + 1];
                s1 += acc[i][j][2] * avec[n] + acc[i][j][3] * avec[n + 1];
            }
            s0 += __shfl_xor_sync(0xffffffffu, s0, 1);
            s0 += __shfl_xor_sync(0xffffffffu, s0, 2);
            s1 += __shfl_xor_sync(0xffffffffu, s1, 1);
            s1 += __shfl_xor_sync(0xffffffffu, s1, 2);
            if ((lane & 3) == 0) {
                atomicAdd(&s_sm[m0 + qm], s0);
                atomicAdd(&s_sm[m0 + 8 + qm], s1);
            }
        }
    } else {
        #pragma unroll
        for (int i = 0; i < 2; ++i) {
            #pragma unroll
            for (int j = 0; j < 8; ++j) {
                int m0 = rowBase + wm * 32 + i * 16;
                int n  = (wn - 2) * 64 + j * 8 + qn;
                int r0 = m0 + qm, r1 = m0 + 8 + qm;
                if (r0 < B_NODES) {
                    __half2 h = __float22half2_rn(make_float2(acc[i][j][0], acc[i][j][1]));
                    *(__half2*)(g_partial16 + (size_t)r0 * D_DIM + n) = h;
                }
                if (r1 < B_NODES) {
                    __half2 h = __float22half2_rn(make_float2(acc[i][j][2], acc[i][j][3]));
                    *(__half2*)(g_partial16 + (size_t)r1 * D_DIM + n) = h;
                }
            }
        }
    }
    __syncthreads();
    if (tid < 128 && rowBase + tid < B_NODES) g_s[rowBase + tid] = s_sm[tid];
}

// ---------------------------------------------------------------------------
// Neighbor pass: h = fn @ W, 128x128 tile, BK=64, 256 thr, 2 CTA/SM. (round-13)
// ---------------------------------------------------------------------------
__global__ void __launch_bounds__(256, 2)
neigh_kernel(const float* __restrict__ fn, const float* __restrict__ avec)
{
    constexpr int NCHUNK = F_DIM / 64;

    extern __shared__ char dsm[];
    const uint32_t ab = (smem_u32(dsm) + 1023u) & ~1023u;

    const int tid = threadIdx.x;
    const int lane = tid & 31;
    const int wm = (tid >> 5) & 3;
    const int wn = (tid >> 5) >> 2;
    const int rowBase = blockIdx.x * 128;

    float acc[2][8][4];
    #pragma unroll
    for (int i = 0; i < 2; ++i)
        #pragma unroll
        for (int j = 0; j < 8; ++j)
            #pragma unroll
            for (int q = 0; q < 4; ++q) acc[i][j][q] = 0.f;

    const int lr = lane & 7;
    const int lg = lane >> 3;

    float4 sa0[4], sa1[4];

    auto stA = [&](int s) { return ab + (uint32_t)s * 32768u; };
    auto stB = [&](int s) { return ab + (uint32_t)s * 32768u + 16384u; };

    auto issueLoads = [&](int c, int s) {
        const int k0c = c * 64;
        #pragma unroll
        for (int i = 0; i < 4; ++i) {
            int idx = tid + i * 256;
            int row = idx >> 3, seg = idx & 7;
            int grow = rowBase + row;
            sa0[i] = make_float4(0.f, 0.f, 0.f, 0.f);
            sa1[i] = sa0[i];
            if (grow < U_NODES) {
                const float* src = fn + (size_t)grow * F_DIM + k0c + seg * 8;
                sa0[i] = *(const float4*)(src);
                sa1[i] = *(const float4*)(src + 4);
            }
        }
        #pragma unroll
        for (int i = 0; i < 4; ++i) {
            int idx = tid + i * 256;
            int row = idx >> 3, seg = idx & 7;
            uint32_t off = SMEM_SWIZZLE_128B((uint32_t)(row * 128 + seg * 16));
            cp_async16(stB(s) + off, g_W16_1 + (size_t)row * F_DIM + k0c + seg * 8);
        }
        CP_ASYNC_COMMIT();
    };

    auto commitLoads = [&](int s) {
        #pragma unroll
        for (int i = 0; i < 4; ++i) {
            int idx = tid + i * 256;
            int row = idx >> 3, seg = idx & 7;
            uint32_t w0 = pack_h2(sa0[i].x, sa0[i].y);
            uint32_t w1 = pack_h2(sa0[i].z, sa0[i].w);
            uint32_t w2 = pack_h2(sa1[i].x, sa1[i].y);
            uint32_t w3 = pack_h2(sa1[i].z, sa1[i].w);
            uint32_t off = SMEM_SWIZZLE_128B((uint32_t)(row * 128 + seg * 16));
            STS128(w0, w1, w2, w3, stA(s) + off);
        }
        CP_ASYNC_WAIT0();
    };

    auto computeChunk = [&](int s) {
        #pragma unroll
        for (int t = 0; t < 4; ++t) {
            uint32_t af[2][4];
            #pragma unroll
            for (int i = 0; i < 2; ++i) {
                int row = wm * 32 + i * 16 + lr + (lg & 1) * 8;
                int kb = t * 32 + (lg >> 1) * 16;
                ldm_x4(af[i], stA(s) + SMEM_SWIZZLE_128B((uint32_t)(row * 128 + kb)));
            }
            uint32_t bfr[4][4];
            #pragma unroll
            for (int j = 0; j < 4; ++j) {
                int row = wn * 64 + j * 16 + lr + (lg >> 1) * 8;
                int kb = t * 32 + (lg & 1) * 16;
                ldm_x4(bfr[j], stB(s) + SMEM_SWIZZLE_128B((uint32_t)(row * 128 + kb)));
            }
            #pragma unroll
            for (int i = 0; i < 2; ++i)
                #pragma unroll
                for (int j = 0; j < 4; ++j) {
                    mma_f16(acc[i][2 * j],     af[i], bfr[j][0], bfr[j][1]);
                    mma_f16(acc[i][2 * j + 1], af[i], bfr[j][2], bfr[j][3]);
                }
        }
    };

    issueLoads(0, 0);
    commitLoads(0);
    __syncthreads();

    for (int c = 0; c < NCHUNK; ++c) {
        const int cur = c & 1, nxt = (c + 1) & 1;
        if (c + 1 < NCHUNK) issueLoads(c + 1, nxt);
        computeChunk(cur);
        if (c + 1 < NCHUNK) commitLoads(nxt);
        __syncthreads();
    }

    const int qm = lane >> 2;
    const int qn = (lane & 3) * 2;
    const float* av = avec + D_DIM;

    float* s_sm = (float*)dsm;
    if (tid < 128) s_sm[tid] = 0.f;
    __syncthreads();

    #pragma unroll
    for (int i = 0; i < 2; ++i) {
        int m0 = wm * 32 + i * 16;
        int r0 = rowBase + m0 + qm, r1 = rowBase + m0 + 8 + qm;
        float s0 = 0.f, s1 = 0.f;
        #pragma unroll
        for (int j = 0; j < 8; ++j) {
            int n = wn * 64 + j * 8 + qn;
            float c0 = acc[i][j][0], c1 = acc[i][j][1];
            float c2 = acc[i][j][2], c3 = acc[i][j][3];
            s0 += c0 * av[n] + c1 * av[n + 1];
            s1 += c2 * av[n] + c3 * av[n + 1];
            if (r0 < U_NODES) {
                __half2 h = __float22half2_rn(make_float2(c0, c1));
                *(__half2*)(g_h16 + (size_t)r0 * D_DIM + n) = h;
            }
            if (r1 < U_NODES) {
                __half2 h = __float22half2_rn(make_float2(c2, c3));
                *(__half2*)(g_h16 + (size_t)r1 * D_DIM + n) = h;
            }
        }
        s0 += __shfl_xor_sync(0xffffffffu, s0, 1);
        s0 += __shfl_xor_sync(0xffffffffu, s0, 2);
        s1 += __shfl_xor_sync(0xffffffffu, s1, 1);
        s1 += __shfl_xor_sync(0xffffffffu, s1, 2);
        if ((lane & 3) == 0) {
            atomicAdd(&s_sm[m0 + qm], s0);
            atomicAdd(&s_sm[m0 + 8 + qm], s1);
        }
    }
    __syncthreads();
    if (tid < 128 && rowBase + tid < U_NODES)
        g_s[B_NODES + rowBase + tid] = s_sm[tid];
}

// ---------------------------------------------------------------------------
// GEMM2 with FUSED aggregation:
//   out = relu(partial + [nf | h'] @ Wd[640:1152 | 512:640])
// Chunks 0..7 = nf (Wd k=640+64c); chunks 8,9 = h' (Wd k=512+64(c-8)) read
// from an smem h' tile that this CTA computes itself:
//   - weight pass: 2 thr/node compute 10 normalized exp weights -> smem
//   - gather quarters: during chunks 0..3, gather 32 nodes x 128 cols of
//     h' from g_h16 (L2-resident) into the smem tile (overlaps MMAs)
// smem: 2x32KB stages + 32KB h' tile + 5KB w + 5KB jj (~107KB, 2 CTA/SM).
// ---------------------------------------------------------------------------
__global__ void __launch_bounds__(256, 2)
gemm2_kernel(const float* __restrict__ nf, const int* __restrict__ edge_dst,
             float* __restrict__ outp)
{
    constexpr int NCHUNK = 10;

    extern __shared__ char dsm[];
    const uint32_t base0 = smem_u32(dsm);
    const uint32_t ab = (base0 + 1023u) & ~1023u;
    char* abp = dsm + (ab - base0);

    const uint32_t hp0 = ab + 65536u;          // h' cols 0..63   (16KB)
    const uint32_t hp1 = ab + 81920u;          // h' cols 64..127 (16KB)
    float* w_sm = (float*)(abp + 98304);       // [128][10]
    int*   jj_sm = (int*)(abp + 103424);       // [128][10]

    const int tid = threadIdx.x;
    const int lane = tid & 31;
    const int wm = (tid >> 5) & 3;
    const int wn = (tid >> 5) >> 2;
    const int rowBase = blockIdx.x * 128;

    float acc[2][8][4];
    #pragma unroll
    for (int i = 0; i < 2; ++i)
        #pragma unroll
        for (int j = 0; j < 8; ++j)
            #pragma unroll
            for (int q = 0; q < 4; ++q) acc[i][j][q] = 0.f;

    const int lr = lane & 7;
    const int lg = lane >> 3;

    float4 sa0[4], sa1[4];

    auto stA = [&](int s) { return ab + (uint32_t)s * 32768u; };
    auto stB = [&](int s) { return ab + (uint32_t)s * 32768u + 16384u; };

    // Wd column block for chunk c
    auto kWd = [&](int c) { return (c < 8) ? (640 + c * 64) : (512 + (c - 8) * 64); };

    auto issueLoads = [&](int c, int s) {
        if (c < 8) {
            const int knf = c * 64;
            #pragma unroll
            for (int i = 0; i < 4; ++i) {
                int idx = tid + i * 256;
                int row = idx >> 3, seg = idx & 7;
                int grow = rowBase + row;
                sa0[i] = make_float4(0.f, 0.f, 0.f, 0.f);
                sa1[i] = sa0[i];
                if (grow < B_NODES) {
                    const float* src = nf + (size_t)grow * F_DIM + knf + seg * 8;
                    sa0[i] = *(const float4*)(src);
                    sa1[i] = *(const float4*)(src + 4);
                }
            }
        }
        const int k0 = kWd(c);
        #pragma unroll
        for (int i = 0; i < 4; ++i) {
            int idx = tid + i * 256;
            int row = idx >> 3, seg = idx & 7;
            uint32_t off = SMEM_SWIZZLE_128B((uint32_t)(row * 128 + seg * 16));
            cp_async16(stB(s) + off, g_W16_2 + (size_t)row * KOUT + k0 + seg * 8);
        }
        CP_ASYNC_COMMIT();
    };

    auto commitLoads = [&](int c, int s) {
        if (c < 8) {
            #pragma unroll
            for (int i = 0; i < 4; ++i) {
                int idx = tid + i * 256;
                int row = idx >> 3, seg = idx & 7;
                uint32_t w0 = pack_h2(sa0[i].x, sa0[i].y);
                uint32_t w1 = pack_h2(sa0[i].z, sa0[i].w);
                uint32_t w2 = pack_h2(sa1[i].x, sa1[i].y);
                uint32_t w3 = pack_h2(sa1[i].z, sa1[i].w);
                uint32_t off = SMEM_SWIZZLE_128B((uint32_t)(row * 128 + seg * 16));
                STS128(w0, w1, w2, w3, stA(s) + off);
            }
        }
        CP_ASYNC_WAIT0();
    };

    auto computeChunk = [&](int c, int s) {
        const uint32_t sAaddr = (c < 8) ? stA(s) : ((c == 8) ? hp0 : hp1);
        #pragma unroll
        for (int t = 0; t < 4; ++t) {
            uint32_t af[2][4];
            #pragma unroll
            for (int i = 0; i < 2; ++i) {
                int row = wm * 32 + i * 16 + lr + (lg & 1) * 8;
                int kb = t * 32 + (lg >> 1) * 16;
                ldm_x4(af[i], sAaddr + SMEM_SWIZZLE_128B((uint32_t)(row * 128 + kb)));
            }
            uint32_t bfr[4][4];
            #pragma unroll
            for (int j = 0; j < 4; ++j) {
                int row = wn * 64 + j * 16 + lr + (lg >> 1) * 8;
                int kb = t * 32 + (lg & 1) * 16;
                ldm_x4(bfr[j], stB(s) + SMEM_SWIZZLE_128B((uint32_t)(row * 128 + kb)));
            }
            #pragma unroll
            for (int i = 0; i < 2; ++i)
                #pragma unroll
                for (int j = 0; j < 4; ++j) {
                    mma_f16(acc[i][2 * j],     af[i], bfr[j][0], bfr[j][1]);
                    mma_f16(acc[i][2 * j + 1], af[i], bfr[j][2], bfr[j][3]);
                }
        }
    };

    // gather quarter q: 32 nodes x 64 half2-cols of h' -> smem tile
    auto gatherQuarter = [&](int q) {
        const int col2 = tid & 63;            // half2 column 0..63
        const int slot = tid >> 6;            // 0..3
        const uint32_t tile = (col2 < 32) ? hp0 : hp1;
        const int clb = (col2 & 31) * 4;      // byte offset of half2 in tile row
        #pragma unroll
        for (int r = 0; r < 8; ++r) {
            int nl = q * 32 + slot + r * 4;   // local node 0..127
            int gnode = rowBase + nl;
            float ax = 0.f, ay = 0.f;
            if (gnode < B_NODES) {
                #pragma unroll
                for (int k = 0; k < K_NEIGH; ++k) {
                    float wk = w_sm[nl * K_NEIGH + k];
                    int j = jj_sm[nl * K_NEIGH + k];
                    __half2 hv = *(const __half2*)(g_h16 + (size_t)j * D_DIM + col2 * 2);
                    float2 f = __half22float2(hv);
                    ax += wk * f.x;
                    ay += wk * f.y;
                }
            }
            uint32_t off = SMEM_SWIZZLE_128B((uint32_t)(nl * 128 + clb));
            STS32(tile + off, pack_h2(ax, ay));
        }
    };

    // ---- prologue: start loads, compute normalized weights, commit ----
    issueLoads(0, 0);
    {
        const int node = tid >> 1;            // 0..127
        const int half = tid & 1;
        const int gnode = rowBase + node;
        float wv[5];
        int jv[5];
        float sum5 = 0.f;
        if (gnode < B_NODES) {
            float si = g_s[gnode];
            #pragma unroll
            for (int k2 = 0; k2 < 5; ++k2) {
                int j = edge_dst[(size_t)gnode * K_NEIGH + half * 5 + k2];
                float sc = si + g_s[B_NODES + j];
                float lrr = sc > 0.f ? sc : 0.2f * sc;
                wv[k2] = expf(-lrr);
                sum5 += wv[k2];
                jv[k2] = j;
            }
        } else {
            #pragma unroll
            for (int k2 = 0; k2 < 5; ++k2) { wv[k2] = 0.f; jv[k2] = 0; }
        }
        float other = __shfl_xor_sync(0xffffffffu, sum5, 1);
        float tot = sum5 + other;
        float inv = (gnode < B_NODES && tot > 0.f) ? 1.f / tot : 0.f;
        #pragma unroll
        for (int k2 = 0; k2 < 5; ++k2) {
            w_sm[node * K_NEIGH + half * 5 + k2] = wv[k2] * inv;
            jj_sm[node * K_NEIGH + half * 5 + k2] = jv[k2];
        }
    }
    commitLoads(0, 0);
    __syncthreads();

    // ---- main pipeline; gather quarters overlap chunks 0..3 ----
    for (int c = 0; c < NCHUNK; ++c) {
        const int cur = c & 1, nxt = (c + 1) & 1;
        if (c + 1 < NCHUNK) issueLoads(c + 1, nxt);
        computeChunk(c, cur);
        if (c < 4) gatherQuarter(c);
        if (c + 1 < NCHUNK) commitLoads(c + 1, nxt);
        __syncthreads();
    }

    // ---- epilogue: add fp16 partial, relu, store ----
    const int qm = lane >> 2;
    const int qn = (lane & 3) * 2;
    #pragma unroll
    for (int i = 0; i < 2; ++i) {
        #pragma unroll
        for (int j = 0; j < 8; ++j) {
            int m0 = rowBase + wm * 32 + i * 16;
            int n  = wn * 64 + j * 8 + qn;
            int r0 = m0 + qm, r1 = m0 + 8 + qm;
            if (r0 < B_NODES) {
                __half2 p = *(const __half2*)(g_partial16 + (size_t)r0 * D_DIM + n);
                float2 pf = __half22float2(p);
                float c0 = fmaxf(acc[i][j][0] + pf.x, 0.f);
                float c1 = fmaxf(acc[i][j][1] + pf.y, 0.f);
                *(float2*)(outp + (size_t)r0 * D_DIM + n) = make_float2(c0, c1);
            }
            if (r1 < B_NODES) {
                __half2 p = *(const __half2*)(g_partial16 + (size_t)r1 * D_DIM + n);
                float2 pf = __half22float2(p);
                float c2 = fmaxf(acc[i][j][2] + pf.x, 0.f);
                float c3 = fmaxf(acc[i][j][3] + pf.y, 0.f);
                *(float2*)(outp + (size_t)r1 * D_DIM + n) = make_float2(c2, c3);
            }
        }
    }
}

// ---------------------------------------------------------------------------
// Launch
// Inputs: 0=feats_batch 1=feats_neigh 2=neigh_feats 3=W 4=a 5=Wd 6=edge_src 7=edge_dst
// ---------------------------------------------------------------------------
extern "C" void kernel_launch(void* const* d_in, const int* in_sizes, int n_in,
                              void* d_out, int out_size)
{
    const float* fb   = (const float*)d_in[0];
    const float* fn   = (const float*)d_in[1];
    const float* nf   = (const float*)d_in[2];
    const float* W    = (const float*)d_in[3];
    const float* avec = (const float*)d_in[4];
    const float* Wd   = (const float*)d_in[5];
    const int* edge_dst = (const int*)d_in[7];
    float* out = (float*)d_out;
    (void)in_sizes; (void)n_in; (void)out_size;

    const int SMEM_FB  = 99328;    // 2 x 48KB + align
    const int SMEM_STD = 66560;    // 2 x 32KB + align
    const int SMEM_G2  = 109568;   // 2 x 32KB + 32KB h' + 10KB w/jj + align
    cudaFuncSetAttribute(fb_kernel,    cudaFuncAttributeMaxDynamicSharedMemorySize, SMEM_FB);
    cudaFuncSetAttribute(neigh_kernel, cudaFuncAttributeMaxDynamicSharedMemorySize, SMEM_STD);
    cudaFuncSetAttribute(gemm2_kernel, cudaFuncAttributeMaxDynamicSharedMemorySize, SMEM_G2);

    // 0) weight converts
    convertW_kernel<1><<<(F_DIM * D_DIM + 255) / 256, 256>>>(W);
    convertW_kernel<2><<<(KOUT * D_DIM + 255) / 256, 256>>>(Wd);

    // 1) fb pass: N=256 concat GEMM -> s[0:B] + partial16
    fb_kernel<<<(B_NODES + 127) / 128, 512, SMEM_FB>>>(fb, avec);

    // 2) neighbor pass: s[B:] + h16 = fn@W
    neigh_kernel<<<(U_NODES + 127) / 128, 256, SMEM_STD>>>(fn, avec);

    // 3) gemm2 with fused aggregation: out = relu(partial + [nf|h']@Wd[512:])
    gemm2_kernel<<<(B_NODES + 127) / 128, 256, SMEM_G2>>>(nf, edge_dst, out);
}

// round 15
// speedup vs baseline: 1.2446x; 1.2446x over previous
#include <cuda_runtime.h>
#include <cuda_fp16.h>
#include <cstdint>

// Problem constants
#define B_NODES 100000
#define U_NODES 50000
#define NTOT    150000
#define F_DIM   512
#define D_DIM   128
#define K_NEIGH 10
#define KOUT    1152

#define FB_BLOCKS ((B_NODES + 127) / 128)   // 782
#define NB_BLOCKS ((U_NODES + 127) / 128)   // 391

#define SMEM_SWIZZLE_128B(byte_offset) ((byte_offset) ^ (((byte_offset) >> 3) & 0x70))

// ---------------------------------------------------------------------------
// Warp-level tensor-core primitives
// ---------------------------------------------------------------------------
__device__ __forceinline__ uint32_t smem_u32(const void* p) {
    uint32_t a;
    asm("{ .reg .u64 t; cvta.to.shared.u64 t, %1; cvt.u32.u64 %0, t; }" : "=r"(a) : "l"(p));
    return a;
}

__device__ __forceinline__ void ldm_x4(uint32_t* r, uint32_t addr) {
    asm volatile("ldmatrix.sync.aligned.m8n8.x4.shared.b16 {%0,%1,%2,%3}, [%4];"
        : "=r"(r[0]), "=r"(r[1]), "=r"(r[2]), "=r"(r[3]) : "r"(addr));
}

__device__ __forceinline__ void mma_f16(float* c, const uint32_t* a,
                                        uint32_t b0, uint32_t b1) {
    asm volatile("mma.sync.aligned.m16n8k16.row.col.f32.f16.f16.f32 "
        "{%0,%1,%2,%3}, {%4,%5,%6,%7}, {%8,%9}, {%0,%1,%2,%3};"
        : "+f"(c[0]), "+f"(c[1]), "+f"(c[2]), "+f"(c[3])
        : "r"(a[0]), "r"(a[1]), "r"(a[2]), "r"(a[3]), "r"(b0), "r"(b1));
}

__device__ __forceinline__ uint32_t pack_h2(float x, float y) {
    __half2 h = __float22half2_rn(make_float2(x, y));
    return *reinterpret_cast<uint32_t*>(&h);
}

__device__ __forceinline__ void cp_async16(uint32_t dst, const void* src) {
    asm volatile("cp.async.cg.shared.global [%0], [%1], 16;" :: "r"(dst), "l"(src) : "memory");
}
#define CP_ASYNC_COMMIT() asm volatile("cp.async.commit_group;" ::: "memory")
#define CP_ASYNC_WAIT0()  asm volatile("cp.async.wait_group 0;" ::: "memory")

#define STS128(a0, a1, a2, a3, addr) \
    asm volatile("st.shared.v4.b32 [%0], {%1, %2, %3, %4};" \
        :: "r"(addr), "r"(a0), "r"(a1), "r"(a2), "r"(a3) : "memory")

// ---------------------------------------------------------------------------
// Device-global scratch (device-code references only)
// ---------------------------------------------------------------------------
__device__ float g_s[NTOT];
__device__ __align__(16) __half g_h16[(size_t)U_NODES * D_DIM];
// h' [B+pad][128]; pad covers cp.async OOB rows in gemm2's last CTA
__device__ __align__(16) __half g_hprime16[(size_t)(B_NODES + 256) * D_DIM];
__device__ __align__(16) __half g_partial16[(size_t)B_NODES * D_DIM];
__device__ __align__(16) __half g_W16_1[(size_t)D_DIM * F_DIM];
__device__ __align__(16) __half g_W16_2[(size_t)D_DIM * KOUT];

// ---------------------------------------------------------------------------
// Merged weight transpose + fp16 rounding (one launch for W and Wd)
// ---------------------------------------------------------------------------
__global__ void convertW_kernel(const float* __restrict__ W,
                                const float* __restrict__ Wd)
{
    int idx = blockIdx.x * blockDim.x + threadIdx.x;
    if (idx < F_DIM * D_DIM) {
        int k = idx >> 7, n = idx & 127;
        g_W16_1[(size_t)n * F_DIM + k] = __float2half_rn(W[idx]);
    } else {
        int id2 = idx - F_DIM * D_DIM;
        if (id2 >= KOUT * D_DIM) return;
        int k = id2 >> 7, n = id2 & 127;
        g_W16_2[(size_t)n * KOUT + k] = __float2half_rn(Wd[id2]);
    }
}

// ---------------------------------------------------------------------------
// UNIFIED fb+neigh kernel, 512 threads, 96KB dynamic smem, 1 CTA/SM.
//  blocks [0, FB_BLOCKS):  fb pass — N=256 concat GEMM [W | Wd[0:512]], K=512,
//      128x256 tile, 16 warps 4Mx4N (warp tile 32x64).
//      Epilogue: cols [0,128) -> s[0:B]; cols [128,256) -> fp16 partial.
//  blocks [FB_BLOCKS, +NB_BLOCKS): neigh pass — h = fn@W, 128x128 tile,
//      16 warps 4Mx4N (warp tile 32x32). Epilogue: s[B:] + fp16 h16.
// ---------------------------------------------------------------------------
__global__ void __launch_bounds__(512, 1)
fbneigh_kernel(const float* __restrict__ fb, const float* __restrict__ fn,
               const float* __restrict__ avec)
{
    constexpr int NCHUNK = F_DIM / 64;   // 8

    extern __shared__ char dsm[];
    const uint32_t ab = (smem_u32(dsm) + 1023u) & ~1023u;

    const int tid = threadIdx.x;
    const int lane = tid & 31;
    const int wid = tid >> 5;        // 0..15
    const int wm = wid & 3;
    const int wn = wid >> 2;
    const int lr = lane & 7;
    const int lg = lane >> 3;
    const int qm = lane >> 2;
    const int qn = (lane & 3) * 2;

    if (blockIdx.x < FB_BLOCKS) {
        // ================= FB PATH (round-13 fb_kernel verbatim) =============
        const int rowBase = blockIdx.x * 128;

        float acc[2][8][4];
        #pragma unroll
        for (int i = 0; i < 2; ++i)
            #pragma unroll
            for (int j = 0; j < 8; ++j)
                #pragma unroll
                for (int q = 0; q < 4; ++q) acc[i][j][q] = 0.f;

        float4 sa0[2], sa1[2];

        auto stA = [&](int s) { return ab + (uint32_t)s * 49152u; };
        auto stB = [&](int s) { return ab + (uint32_t)s * 49152u + 16384u; };

        auto issueLoads = [&](int c, int s) {
            const int k0c = c * 64;
            #pragma unroll
            for (int i = 0; i < 2; ++i) {
                int idx = tid + i * 512;
                int row = idx >> 3, seg = idx & 7;
                int grow = rowBase + row;
                sa0[i] = make_float4(0.f, 0.f, 0.f, 0.f);
                sa1[i] = sa0[i];
                if (grow < B_NODES) {
                    const float* src = fb + (size_t)grow * F_DIM + k0c + seg * 8;
                    sa0[i] = *(const float4*)(src);
                    sa1[i] = *(const float4*)(src + 4);
                }
            }
            #pragma unroll
            for (int i = 0; i < 4; ++i) {
                int idx = tid + i * 512;
                int row = idx >> 3, seg = idx & 7;
                uint32_t off = SMEM_SWIZZLE_128B((uint32_t)(row * 128 + seg * 16));
                const __half* src = (row < 128)
                    ? g_W16_1 + (size_t)row * F_DIM + k0c + seg * 8
                    : g_W16_2 + (size_t)(row - 128) * KOUT + k0c + seg * 8;
                cp_async16(stB(s) + off, src);
            }
            CP_ASYNC_COMMIT();
        };

        auto commitLoads = [&](int s) {
            #pragma unroll
            for (int i = 0; i < 2; ++i) {
                int idx = tid + i * 512;
                int row = idx >> 3, seg = idx & 7;
                uint32_t w0 = pack_h2(sa0[i].x, sa0[i].y);
                uint32_t w1 = pack_h2(sa0[i].z, sa0[i].w);
                uint32_t w2 = pack_h2(sa1[i].x, sa1[i].y);
                uint32_t w3 = pack_h2(sa1[i].z, sa1[i].w);
                uint32_t off = SMEM_SWIZZLE_128B((uint32_t)(row * 128 + seg * 16));
                STS128(w0, w1, w2, w3, stA(s) + off);
            }
            CP_ASYNC_WAIT0();
        };

        auto computeChunk = [&](int s) {
            #pragma unroll
            for (int t = 0; t < 4; ++t) {
                uint32_t af[2][4];
                #pragma unroll
                for (int i = 0; i < 2; ++i) {
                    int row = wm * 32 + i * 16 + lr + (lg & 1) * 8;
                    int kb = t * 32 + (lg >> 1) * 16;
                    ldm_x4(af[i], stA(s) + SMEM_SWIZZLE_128B((uint32_t)(row * 128 + kb)));
                }
                uint32_t bfr[4][4];
                #pragma unroll
                for (int j = 0; j < 4; ++j) {
                    int row = wn * 64 + j * 16 + lr + (lg >> 1) * 8;
                    int kb = t * 32 + (lg & 1) * 16;
                    ldm_x4(bfr[j], stB(s) + SMEM_SWIZZLE_128B((uint32_t)(row * 128 + kb)));
                }
                #pragma unroll
                for (int i = 0; i < 2; ++i)
                    #pragma unroll
                    for (int j = 0; j < 4; ++j) {
                        mma_f16(acc[i][2 * j],     af[i], bfr[j][0], bfr[j][1]);
                        mma_f16(acc[i][2 * j + 1], af[i], bfr[j][2], bfr[j][3]);
                    }
            }
        };

        issueLoads(0, 0);
        commitLoads(0);
        __syncthreads();

        for (int c = 0; c < NCHUNK; ++c) {
            const int cur = c & 1, nxt = (c + 1) & 1;
            if (c + 1 < NCHUNK) issueLoads(c + 1, nxt);
            computeChunk(cur);
            if (c + 1 < NCHUNK) commitLoads(nxt);
            __syncthreads();
        }

        float* s_sm = (float*)dsm;
        if (tid < 128) s_sm[tid] = 0.f;
        __syncthreads();

        if (wn < 2) {
            #pragma unroll
            for (int i = 0; i < 2; ++i) {
                int m0 = wm * 32 + i * 16;
                float s0 = 0.f, s1 = 0.f;
                #pragma unroll
                for (int j = 0; j < 8; ++j) {
                    int n = wn * 64 + j * 8 + qn;
                    s0 += acc[i][j][0] * avec[n] + acc[i][j][1] * avec[n + 1];
                    s1 += acc[i][j][2] * avec[n] + acc[i][j][3] * avec[n + 1];
                }
                s0 += __shfl_xor_sync(0xffffffffu, s0, 1);
                s0 += __shfl_xor_sync(0xffffffffu, s0, 2);
                s1 += __shfl_xor_sync(0xffffffffu, s1, 1);
                s1 += __shfl_xor_sync(0xffffffffu, s1, 2);
                if ((lane & 3) == 0) {
                    atomicAdd(&s_sm[m0 + qm], s0);
                    atomicAdd(&s_sm[m0 + 8 + qm], s1);
                }
            }
        } else {
            #pragma unroll
            for (int i = 0; i < 2; ++i) {
                #pragma unroll
                for (int j = 0; j < 8; ++j) {
                    int m0 = rowBase + wm * 32 + i * 16;
                    int n  = (wn - 2) * 64 + j * 8 + qn;
                    int r0 = m0 + qm, r1 = m0 + 8 + qm;
                    if (r0 < B_NODES) {
                        __half2 h = __float22half2_rn(make_float2(acc[i][j][0], acc[i][j][1]));
                        *(__half2*)(g_partial16 + (size_t)r0 * D_DIM + n) = h;
                    }
                    if (r1 < B_NODES) {
                        __half2 h = __float22half2_rn(make_float2(acc[i][j][2], acc[i][j][3]));
                        *(__half2*)(g_partial16 + (size_t)r1 * D_DIM + n) = h;
                    }
                }
            }
        }
        __syncthreads();
        if (tid < 128 && rowBase + tid < B_NODES) g_s[rowBase + tid] = s_sm[tid];

    } else {
        // ================= NEIGH PATH: h = fn @ W, 128x128, 16 warps =========
        const int rowBase = (blockIdx.x - FB_BLOCKS) * 128;

        float acc[2][4][4];
        #pragma unroll
        for (int i = 0; i < 2; ++i)
            #pragma unroll
            for (int j = 0; j < 4; ++j)
                #pragma unroll
                for (int q = 0; q < 4; ++q) acc[i][j][q] = 0.f;

        float4 sa0[2], sa1[2];

        auto stA = [&](int s) { return ab + (uint32_t)s * 32768u; };
        auto stB = [&](int s) { return ab + (uint32_t)s * 32768u + 16384u; };

        auto issueLoads = [&](int c, int s) {
            const int k0c = c * 64;
            #pragma unroll
            for (int i = 0; i < 2; ++i) {
                int idx = tid + i * 512;
                int row = idx >> 3, seg = idx & 7;
                int grow = rowBase + row;
                sa0[i] = make_float4(0.f, 0.f, 0.f, 0.f);
                sa1[i] = sa0[i];
                if (grow < U_NODES) {
                    const float* src = fn + (size_t)grow * F_DIM + k0c + seg * 8;
                    sa0[i] = *(const float4*)(src);
                    sa1[i] = *(const float4*)(src + 4);
                }
            }
            #pragma unroll
            for (int i = 0; i < 2; ++i) {
                int idx = tid + i * 512;
                int row = idx >> 3, seg = idx & 7;
                uint32_t off = SMEM_SWIZZLE_128B((uint32_t)(row * 128 + seg * 16));
                cp_async16(stB(s) + off, g_W16_1 + (size_t)row * F_DIM + k0c + seg * 8);
            }
            CP_ASYNC_COMMIT();
        };

        auto commitLoads = [&](int s) {
            #pragma unroll
            for (int i = 0; i < 2; ++i) {
                int idx = tid + i * 512;
                int row = idx >> 3, seg = idx & 7;
                uint32_t w0 = pack_h2(sa0[i].x, sa0[i].y);
                uint32_t w1 = pack_h2(sa0[i].z, sa0[i].w);
                uint32_t w2 = pack_h2(sa1[i].x, sa1[i].y);
                uint32_t w3 = pack_h2(sa1[i].z, sa1[i].w);
                uint32_t off = SMEM_SWIZZLE_128B((uint32_t)(row * 128 + seg * 16));
                STS128(w0, w1, w2, w3, stA(s) + off);
            }
            CP_ASYNC_WAIT0();
        };

        auto computeChunk = [&](int s) {
            #pragma unroll
            for (int t = 0; t < 4; ++t) {
                uint32_t af[2][4];
                #pragma unroll
                for (int i = 0; i < 2; ++i) {
                    int row = wm * 32 + i * 16 + lr + (lg & 1) * 8;
                    int kb = t * 32 + (lg >> 1) * 16;
                    ldm_x4(af[i], stA(s) + SMEM_SWIZZLE_128B((uint32_t)(row * 128 + kb)));
                }
                uint32_t bfr[2][4];
                #pragma unroll
                for (int j = 0; j < 2; ++j) {
                    int row = wn * 32 + j * 16 + lr + (lg >> 1) * 8;
                    int kb = t * 32 + (lg & 1) * 16;
                    ldm_x4(bfr[j], stB(s) + SMEM_SWIZZLE_128B((uint32_t)(row * 128 + kb)));
                }
                #pragma unroll
                for (int i = 0; i < 2; ++i)
                    #pragma unroll
                    for (int j = 0; j < 2; ++j) {
                        mma_f16(acc[i][2 * j],     af[i], bfr[j][0], bfr[j][1]);
                        mma_f16(acc[i][2 * j + 1], af[i], bfr[j][2], bfr[j][3]);
                    }
            }
        };

        issueLoads(0, 0);
        commitLoads(0);
        __syncthreads();

        for (int c = 0; c < NCHUNK; ++c) {
            const int cur = c & 1, nxt = (c + 1) & 1;
            if (c + 1 < NCHUNK) issueLoads(c + 1, nxt);
            computeChunk(cur);
            if (c + 1 < NCHUNK) commitLoads(nxt);
            __syncthreads();
        }

        // Epilogue: s (a[128:256], smem-reduced) + fp16 h16
        const float* av = avec + D_DIM;
        float* s_sm = (float*)dsm;
        if (tid < 128) s_sm[tid] = 0.f;
        __syncthreads();

        #pragma unroll
        for (int i = 0; i < 2; ++i) {
            int m0 = wm * 32 + i * 16;
            int r0 = rowBase + m0 + qm, r1 = rowBase + m0 + 8 + qm;
            float s0 = 0.f, s1 = 0.f;
            #pragma unroll
            for (int j = 0; j < 4; ++j) {
                int n = wn * 32 + j * 8 + qn;
                float c0 = acc[i][j][0], c1 = acc[i][j][1];
                float c2 = acc[i][j][2], c3 = acc[i][j][3];
                s0 += c0 * av[n] + c1 * av[n + 1];
                s1 += c2 * av[n] + c3 * av[n + 1];
                if (r0 < U_NODES) {
                    __half2 h = __float22half2_rn(make_float2(c0, c1));
                    *(__half2*)(g_h16 + (size_t)r0 * D_DIM + n) = h;
                }
                if (r1 < U_NODES) {
                    __half2 h = __float22half2_rn(make_float2(c2, c3));
                    *(__half2*)(g_h16 + (size_t)r1 * D_DIM + n) = h;
                }
            }
            s0 += __shfl_xor_sync(0xffffffffu, s0, 1);
            s0 += __shfl_xor_sync(0xffffffffu, s0, 2);
            s1 += __shfl_xor_sync(0xffffffffu, s1, 1);
            s1 += __shfl_xor_sync(0xffffffffu, s1, 2);
            if ((lane & 3) == 0) {
                atomicAdd(&s_sm[m0 + qm], s0);
                atomicAdd(&s_sm[m0 + 8 + qm], s1);
            }
        }
        __syncthreads();
        if (tid < 128 && rowBase + tid < U_NODES)
            g_s[B_NODES + rowBase + tid] = s_sm[tid];
    }
}

// ---------------------------------------------------------------------------
// Aggregation: 4 nodes per block, 64 threads/node, half2 columns. (round-13)
// ---------------------------------------------------------------------------
__global__ void __launch_bounds__(256) agg_kernel(const int* __restrict__ edge_dst)
{
    const int g  = threadIdx.x >> 6;
    const int t2 = threadIdx.x & 63;
    const int i  = blockIdx.x * 4 + g;

    __shared__ float w[4][K_NEIGH];
    __shared__ int   jj[4][K_NEIGH];
    if (i < B_NODES && t2 < K_NEIGH) {
        int j = edge_dst[(size_t)i * K_NEIGH + t2];
        float sc = g_s[i] + g_s[B_NODES + j];
        float lr = sc > 0.f ? sc : 0.2f * sc;
        w[g][t2]  = expf(-lr);
        jj[g][t2] = j;
    }
    __syncthreads();
    if (i >= B_NODES) return;

    float ax = 0.f, ay = 0.f, tot = 0.f;
    #pragma unroll
    for (int k = 0; k < K_NEIGH; ++k) {
        float wk = w[g][k];
        tot += wk;
        __half2 hv = *(const __half2*)(g_h16 + (size_t)jj[g][k] * D_DIM + t2 * 2);
        float2 f = __half22float2(hv);
        ax += wk * f.x;
        ay += wk * f.y;
    }
    float vx = ax / tot, vy = ay / tot;
    if (!isfinite(vx)) vx = 0.f;
    if (!isfinite(vy)) vy = 0.f;
    *(__half2*)(g_hprime16 + (size_t)i * D_DIM + t2 * 2) =
        __float22half2_rn(make_float2(vx, vy));
}

// ---------------------------------------------------------------------------
// GEMM2: out = relu(partial + [h'|nf] @ Wd[512:1152])  (round-13 verbatim)
// ---------------------------------------------------------------------------
__global__ void __launch_bounds__(256, 2)
gemm2_kernel(const float* __restrict__ nf, float* __restrict__ outp)
{
    constexpr int NCHUNK = 10;

    extern __shared__ char dsm[];
    const uint32_t ab = (smem_u32(dsm) + 1023u) & ~1023u;

    const int tid = threadIdx.x;
    const int lane = tid & 31;
    const int wm = (tid >> 5) & 3;
    const int wn = (tid >> 5) >> 2;
    const int rowBase = blockIdx.x * 128;

    float acc[2][8][4];
    #pragma unroll
    for (int i = 0; i < 2; ++i)
        #pragma unroll
        for (int j = 0; j < 8; ++j)
            #pragma unroll
            for (int q = 0; q < 4; ++q) acc[i][j][q] = 0.f;

    const int lr = lane & 7;
    const int lg = lane >> 3;

    float4 sa0[4], sa1[4];

    auto stA = [&](int s) { return ab + (uint32_t)s * 32768u; };
    auto stB = [&](int s) { return ab + (uint32_t)s * 32768u + 16384u; };

    auto issueLoads = [&](int c, int s) {
        const int k0 = 512 + c * 64;
        if (c < 2) {
            #pragma unroll
            for (int i = 0; i < 4; ++i) {
                int idx = tid + i * 256;
                int row = idx >> 3, seg = idx & 7;
                int grow = rowBase + row;
                uint32_t off = SMEM_SWIZZLE_128B((uint32_t)(row * 128 + seg * 16));
                cp_async16(stA(s) + off,
                           g_hprime16 + (size_t)grow * D_DIM + (k0 - 512) + seg * 8);
            }
        } else {
            #pragma unroll
            for (int i = 0; i < 4; ++i) {
                int idx = tid + i * 256;
                int row = idx >> 3, seg = idx & 7;
                int grow = rowBase + row;
                sa0[i] = make_float4(0.f, 0.f, 0.f, 0.f);
                sa1[i] = sa0[i];
                if (grow < B_NODES) {
                    const float* src = nf + (size_t)grow * F_DIM + (k0 - 640) + seg * 8;
                    sa0[i] = *(const float4*)(src);
                    sa1[i] = *(const float4*)(src + 4);
                }
            }
        }
        #pragma unroll
        for (int i = 0; i < 4; ++i) {
            int idx = tid + i * 256;
            int row = idx >> 3, seg = idx & 7;
            uint32_t off = SMEM_SWIZZLE_128B((uint32_t)(row * 128 + seg * 16));
            cp_async16(stB(s) + off, g_W16_2 + (size_t)row * KOUT + k0 + seg * 8);
        }
        CP_ASYNC_COMMIT();
    };

    auto commitLoads = [&](int c, int s) {
        if (c >= 2) {
            #pragma unroll
            for (int i = 0; i < 4; ++i) {
                int idx = tid + i * 256;
                int row = idx >> 3, seg = idx & 7;
                uint32_t w0 = pack_h2(sa0[i].x, sa0[i].y);
                uint32_t w1 = pack_h2(sa0[i].z, sa0[i].w);
                uint32_t w2 = pack_h2(sa1[i].x, sa1[i].y);
                uint32_t w3 = pack_h2(sa1[i].z, sa1[i].w);
                uint32_t off = SMEM_SWIZZLE_128B((uint32_t)(row * 128 + seg * 16));
                STS128(w0, w1, w2, w3, stA(s) + off);
            }
        }
        CP_ASYNC_WAIT0();
    };

    auto computeChunk = [&](int s) {
        #pragma unroll
        for (int t = 0; t < 4; ++t) {
            uint32_t af[2][4];
            #pragma unroll
            for (int i = 0; i < 2; ++i) {
                int row = wm * 32 + i * 16 + lr + (lg & 1) * 8;
                int kb = t * 32 + (lg >> 1) * 16;
                ldm_x4(af[i], stA(s) + SMEM_SWIZZLE_128B((uint32_t)(row * 128 + kb)));
            }
            uint32_t bfr[4][4];
            #pragma unroll
            for (int j = 0; j < 4; ++j) {
                int row = wn * 64 + j * 16 + lr + (lg >> 1) * 8;
                int kb = t * 32 + (lg & 1) * 16;
                ldm_x4(bfr[j], stB(s) + SMEM_SWIZZLE_128B((uint32_t)(row * 128 + kb)));
            }
            #pragma unroll
            for (int i = 0; i < 2; ++i)
                #pragma unroll
                for (int j = 0; j < 4; ++j) {
                    mma_f16(acc[i][2 * j],     af[i], bfr[j][0], bfr[j][1]);
                    mma_f16(acc[i][2 * j + 1], af[i], bfr[j][2], bfr[j][3]);
                }
        }
    };

    issueLoads(0, 0);
    commitLoads(0, 0);
    __syncthreads();

    for (int c = 0; c < NCHUNK; ++c) {
        const int cur = c & 1, nxt = (c + 1) & 1;
        if (c + 1 < NCHUNK) issueLoads(c + 1, nxt);
        computeChunk(cur);
        if (c + 1 < NCHUNK) commitLoads(c + 1, nxt);
        __syncthreads();
    }

    const int qm = lane >> 2;
    const int qn = (lane & 3) * 2;
    #pragma unroll
    for (int i = 0; i < 2; ++i) {
        #pragma unroll
        for (int j = 0; j < 8; ++j) {
            int m0 = rowBase + wm * 32 + i * 16;
            int n  = wn * 64 + j * 8 + qn;
            int r0 = m0 + qm, r1 = m0 + 8 + qm;
            if (r0 < B_NODES) {
                __half2 p = *(const __half2*)(g_partial16 + (size_t)r0 * D_DIM + n);
                float2 pf = __half22float2(p);
                float c0 = fmaxf(acc[i][j][0] + pf.x, 0.f);
                float c1 = fmaxf(acc[i][j][1] + pf.y, 0.f);
                *(float2*)(outp + (size_t)r0 * D_DIM + n) = make_float2(c0, c1);
            }
            if (r1 < B_NODES) {
                __half2 p = *(const __half2*)(g_partial16 + (size_t)r1 * D_DIM + n);
                float2 pf = __half22float2(p);
                float c2 = fmaxf(acc[i][j][2] + pf.x, 0.f);
                float c3 = fmaxf(acc[i][j][3] + pf.y, 0.f);
                *(float2*)(outp + (size_t)r1 * D_DIM + n) = make_float2(c2, c3);
            }
        }
    }
}

// ---------------------------------------------------------------------------
// Launch
// Inputs: 0=feats_batch 1=feats_neigh 2=neigh_feats 3=W 4=a 5=Wd 6=edge_src 7=edge_dst
// ---------------------------------------------------------------------------
extern "C" void kernel_launch(void* const* d_in, const int* in_sizes, int n_in,
                              void* d_out, int out_size)
{
    const float* fb   = (const float*)d_in[0];
    const float* fn   = (const float*)d_in[1];
    const float* nf   = (const float*)d_in[2];
    const float* W    = (const float*)d_in[3];
    const float* avec = (const float*)d_in[4];
    const float* Wd   = (const float*)d_in[5];
    const int* edge_dst = (const int*)d_in[7];
    float* out = (float*)d_out;
    (void)in_sizes; (void)n_in; (void)out_size;

    const int SMEM_FB  = 99328;    // 2 x 48KB + align
    const int SMEM_STD = 66560;    // 2 x 32KB + align
    cudaFuncSetAttribute(fbneigh_kernel, cudaFuncAttributeMaxDynamicSharedMemorySize, SMEM_FB);
    cudaFuncSetAttribute(gemm2_kernel,   cudaFuncAttributeMaxDynamicSharedMemorySize, SMEM_STD);

    // 0) merged weight convert
    int convN = (F_DIM + KOUT) * D_DIM;
    convertW_kernel<<<(convN + 255) / 256, 256>>>(W, Wd);

    // 1) unified fb + neigh pass (independent work shares one grid -> no tail)
    fbneigh_kernel<<<FB_BLOCKS + NB_BLOCKS, 512, SMEM_FB>>>(fb, fn, avec);

    // 2) aggregation -> fp16 h'
    agg_kernel<<<(B_NODES + 3) / 4, 256>>>(edge_dst);

    // 3) out = relu(partial + [h'|nf]@Wd[512:])
    gemm2_kernel<<<(B_NODES + 127) / 128, 256, SMEM_STD>>>(nf, out);
}